// round 2
// baseline (speedup 1.0000x reference)
#include <cuda_runtime.h>
#include <math.h>

#define Bq 2
#define Lq 1024
#define Aq 14
#define Kq 30
#define NRBF 16
#define EFq 128
#define EDGE_INq 3152
#define Mrows (Bq*Lq*Kq)   // 61440
#define BM 128
#define PQG 28             // Dsm group size (196/28 = 7 groups)

typedef unsigned long long ull;

// ---- scratch (__device__ globals; no allocations allowed) ----
__device__ int   g_Eidx[Mrows];
__device__ __align__(16) float g_X2[Bq*Lq*Aq*3];
__device__ __align__(16) float g_Wt[EDGE_INq*EFq];

__constant__ float c_freq[8] = {
    1.0f, 0.31622776601683794f, 0.1f, 0.031622776601683794f,
    0.01f, 0.0031622776601683794f, 0.001f, 0.00031622776601683794f
};

__device__ __forceinline__ void fma2(ull& d, ull a, ull b) {
    asm("fma.rn.f32x2 %0, %1, %2, %0;" : "+l"(d) : "l"(a), "l"(b));
}
__device__ __forceinline__ float2 ull2f2(ull v) {
    float2 r; asm("mov.b64 {%0, %1}, %2;" : "=f"(r.x), "=f"(r.y) : "l"(v)); return r;
}

// =====================================================================
// Kernel 1: per-(b,i) masked CA distances + iterative top-K=30
// =====================================================================
__global__ void topk_kernel(const float* __restrict__ X,
                            const float* __restrict__ mask,
                            float* __restrict__ out_tail) {
    __shared__ float Da[Lq];
    __shared__ float svals[8];
    __shared__ int   sidx[8];
    __shared__ float sDmax;

    int bi  = blockIdx.x;
    int b   = bi >> 10;
    int i   = bi & (Lq - 1);
    int tid = threadIdx.x;

    const float* Xb = X + (size_t)b * Lq * Aq * 3;
    float cx = Xb[(i*Aq+1)*3+0];
    float cy = Xb[(i*Aq+1)*3+1];
    float cz = Xb[(i*Aq+1)*3+2];
    float mi = mask[b*Lq + i];

    float lmax = 0.f;
    for (int j = tid; j < Lq; j += 256) {
        float dx = cx - Xb[(j*Aq+1)*3+0];
        float dy = cy - Xb[(j*Aq+1)*3+1];
        float dz = cz - Xb[(j*Aq+1)*3+2];
        float m2 = mi * mask[b*Lq + j];
        float D  = m2 * sqrtf(dx*dx + dy*dy + dz*dz + 1e-6f);
        Da[j] = D;
        lmax = fmaxf(lmax, D);
    }
    #pragma unroll
    for (int off = 16; off; off >>= 1)
        lmax = fmaxf(lmax, __shfl_xor_sync(0xffffffffu, lmax, off));
    if ((tid & 31) == 0) svals[tid >> 5] = lmax;
    __syncthreads();
    if (tid == 0) {
        float m = svals[0];
        for (int w = 1; w < 8; w++) m = fmaxf(m, svals[w]);
        sDmax = m;
    }
    __syncthreads();
    float Dmax = sDmax;
    for (int j = tid; j < Lq; j += 256) {
        float m2 = mi * mask[b*Lq + j];
        Da[j] += 2.f * (1.f - m2) * Dmax;
    }
    __syncthreads();

    for (int k = 0; k < Kq; k++) {
        float bv = 3.4e38f; int bj = 0x7fffffff;
        for (int j = tid; j < Lq; j += 256) {
            float v = Da[j];
            if (v < bv) { bv = v; bj = j; }
        }
        #pragma unroll
        for (int off = 16; off; off >>= 1) {
            float ov = __shfl_down_sync(0xffffffffu, bv, off);
            int   oj = __shfl_down_sync(0xffffffffu, bj, off);
            if (ov < bv || (ov == bv && oj < bj)) { bv = ov; bj = oj; }
        }
        if ((tid & 31) == 0) { svals[tid >> 5] = bv; sidx[tid >> 5] = bj; }
        __syncthreads();
        if (tid == 0) {
            for (int w = 1; w < 8; w++) {
                float v = svals[w]; int jj = sidx[w];
                if (v < bv || (v == bv && jj < bj)) { bv = v; bj = jj; }
            }
            int orow = bi * Kq + k;
            g_Eidx[orow] = bj;
            if (out_tail) out_tail[orow] = (float)bj;
            Da[bj] = 3.4e38f;
        }
        __syncthreads();
    }
}

// =====================================================================
// Kernel 2: build X2 = [N, Ca, C, O, Cb, X[5:]]
// =====================================================================
__global__ void buildX2_kernel(const float* __restrict__ X) {
    int t = blockIdx.x * blockDim.x + threadIdx.x;
    if (t >= Bq * Lq) return;
    const float* xr = X + (size_t)t * Aq * 3;
    float* o = g_X2 + (size_t)t * Aq * 3;
    #pragma unroll
    for (int a = 0; a < Aq*3; a++) o[a] = xr[a];
    float Nx = xr[0],  Ny = xr[1],  Nz = xr[2];
    float Cax= xr[3],  Cay= xr[4],  Caz= xr[5];
    float Cx = xr[6],  Cy = xr[7],  Cz = xr[8];
    float bx = Cax - Nx, by = Cay - Ny, bz = Caz - Nz;
    float cx = Cx - Cax, cy = Cy - Cay, cz = Cz - Caz;
    float ax = by*cz - bz*cy;
    float ay = bz*cx - bx*cz;
    float az = bx*cy - by*cx;
    o[12] = -0.58273431f*ax + 0.56802827f*bx - 0.54067466f*cx + Cax;
    o[13] = -0.58273431f*ay + 0.56802827f*by - 0.54067466f*cy + Cay;
    o[14] = -0.58273431f*az + 0.56802827f*bz - 0.54067466f*cz + Caz;
}

// =====================================================================
// Kernel 3: transpose W (128 x 3152) -> Wt (3152 x 128)
// =====================================================================
__global__ void transposeW_kernel(const float* __restrict__ W) {
    int t = blockIdx.x * blockDim.x + threadIdx.x;
    if (t < EFq * EDGE_INq) {
        int f = t / EDGE_INq;
        int c = t - f * EDGE_INq;
        g_Wt[c * EFq + f] = W[t];
    }
}

// =====================================================================
// Kernel 4: fused feature-gen + SGEMM + LayerNorm
// BM=128 rows, BN=128 cols, BK=16. 256 threads, 8x8 microtile via FFMA2.
// As2 stores each A value DUPLICATED (v,v) so fma.rn.f32x2 needs no packing.
// =====================================================================
// smem float offsets
#define OFF_XI   0
#define OFF_XJ   5376
#define OFF_AMI  10752
#define OFF_AMJ  12544
#define OFF_DSM  14336          // 28*128
#define OFF_AS2  17920          // 16*256 (dup)
#define OFF_BS   22016          // 16*128
#define OFF_DPOS 24064          // 128
#define SMEM_FLOATS 24192
#define SMEM_BYTES  (SMEM_FLOATS*4 + 256*4)   // + iidx/jidx = 97792 B

__global__ void __launch_bounds__(256, 2)
fused_gemm_kernel(const float* __restrict__ atom_mask,
                  const float* __restrict__ gamma_,
                  const float* __restrict__ beta_,
                  float* __restrict__ out) {
    extern __shared__ float sm[];
    float* xi   = sm + OFF_XI;
    float* xj   = sm + OFF_XJ;
    float* ami  = sm + OFF_AMI;
    float* amj  = sm + OFF_AMJ;
    float* Dsm  = sm + OFF_DSM;
    float* As2  = sm + OFF_AS2;
    float* Bs   = sm + OFF_BS;
    float* dpos = sm + OFF_DPOS;
    int*   iidx = (int*)(sm + SMEM_FLOATS);
    int*   jidx = iidx + BM;

    int tid  = threadIdx.x;
    int row0 = blockIdx.x * BM;          // 480 blocks exactly

    if (tid < BM) {
        int gr  = row0 + tid;
        int b   = gr / (Lq * Kq);
        int rem = gr - b * (Lq * Kq);
        int i   = rem / Kq;
        int j   = g_Eidx[gr];
        iidx[tid] = b * Lq + i;
        jidx[tid] = b * Lq + j;
        dpos[tid] = (float)(j - i);
    }
    __syncthreads();
    for (int e = tid; e < BM*42; e += 256) {
        int r = e / 42, c = e - r*42;
        xi[e] = g_X2[iidx[r]*42 + c];
        xj[e] = g_X2[jidx[r]*42 + c];
    }
    for (int e = tid; e < BM*14; e += 256) {
        int r = e / 14, c = e - r*14;
        ami[e] = 1.f - atom_mask[iidx[r]*14 + c];
        amj[e] = 1.f - atom_mask[jidx[r]*14 + c];
    }

    int tx = tid & 15;                   // col group: cols tx*8..+7
    int ry = tid >> 4;                   // row group: rows ry*8..+7
    ull acc2[8][4];
    #pragma unroll
    for (int u = 0; u < 8; u++)
        #pragma unroll
        for (int c = 0; c < 4; c++) acc2[u][c] = 0ull;

    for (int ch = 0; ch < 197; ch++) {
        __syncthreads();                 // As2/Bs reuse barrier (also covers init loads at ch=0)
        // ---- load B tile (16 x 128) from transposed W ----
        #pragma unroll
        for (int u = 0; u < 2; u++) {
            int e4 = tid + u*256;
            int kk = e4 >> 5;
            int f4 = e4 & 31;
            ((float4*)Bs)[e4] =
                ((const float4*)(g_Wt + (size_t)((ch << 4) + kk) * EFq))[f4];
        }
        // ---- generate A tile (duplicated layout: As2[k*256 + row*2 + {0,1}]) ----
        if (ch == 0) {
            if (tid < BM) {
                float d = dpos[tid];
                #pragma unroll
                for (int m = 0; m < 8; m++) {
                    float s, c;
                    sincosf(d * c_freq[m], &s, &c);
                    *(float2*)&As2[ m    *256 + tid*2] = make_float2(c, c);
                    *(float2*)&As2[(m+8) *256 + tid*2] = make_float2(s, s);
                }
            }
        } else {
            int pq  = ch - 1;
            int pqL = pq % PQG;
            if (pqL == 0) {              // uniform branch: refill Dsm group
                for (int e = tid; e < PQG*BM; e += 256) {
                    int pl = e >> 7, r = e & 127;
                    int pp = pq + pl;
                    int p = pp / 14, q = pp - p*14;
                    float dx = xi[r*42 + p*3+0] - xj[r*42 + q*3+0];
                    float dy = xi[r*42 + p*3+1] - xj[r*42 + q*3+1];
                    float dz = xi[r*42 + p*3+2] - xj[r*42 + q*3+2];
                    Dsm[e] = sqrtf(dx*dx + dy*dy + dz*dz + 1e-6f);
                }
                __syncthreads();
            }
            int p = pq / 14, q = pq - p*14;
            int row = tid & 127;
            float D  = Dsm[(pqL << 7) + row];
            float co = ami[row*14 + p] * amj[row*14 + q];
            int r0 = (tid >> 7) << 3;    // rbf 0..7 or 8..15
            #pragma unroll
            for (int rr = 0; rr < 8; rr++) {
                int r = r0 + rr;
                float x = (D - (float)r * (20.f/15.f)) * 0.8f;
                float v = co * __expf(-x*x);
                *(float2*)&As2[r*256 + row*2] = make_float2(v, v);
            }
        }
        __syncthreads();
        // ---- FFMA2 micro-tile: 8 rows x 8 cols (4 pairs) per thread ----
        #pragma unroll
        for (int kk = 0; kk < 16; kk++) {
            const ulonglong2* Ap = (const ulonglong2*)&As2[(kk << 8) + (ry << 4)];
            ulonglong2 a0 = Ap[0], a1 = Ap[1], a2 = Ap[2], a3 = Ap[3];
            const ulonglong2* Bp = (const ulonglong2*)&Bs[(kk << 7) + (tx << 3)];
            ulonglong2 b0 = Bp[0], b1 = Bp[1];
            ull av[8] = {a0.x, a0.y, a1.x, a1.y, a2.x, a2.y, a3.x, a3.y};
            ull bv[4] = {b0.x, b0.y, b1.x, b1.y};
            #pragma unroll
            for (int u = 0; u < 8; u++)
                #pragma unroll
                for (int c = 0; c < 4; c++)
                    fma2(acc2[u][c], av[u], bv[c]);
        }
    }

    // ---- LayerNorm epilogue: row spread across 16 lanes (same ry) ----
    float4 g4a = *(const float4*)&gamma_[tx << 3];
    float4 g4b = *(const float4*)&gamma_[(tx << 3) + 4];
    float4 b4a = *(const float4*)&beta_ [tx << 3];
    float4 b4b = *(const float4*)&beta_ [(tx << 3) + 4];
    #pragma unroll
    for (int u = 0; u < 8; u++) {
        float2 f0 = ull2f2(acc2[u][0]);
        float2 f1 = ull2f2(acc2[u][1]);
        float2 f2 = ull2f2(acc2[u][2]);
        float2 f3 = ull2f2(acc2[u][3]);
        float s = f0.x+f0.y + f1.x+f1.y + f2.x+f2.y + f3.x+f3.y;
        #pragma unroll
        for (int off = 8; off; off >>= 1) s += __shfl_xor_sync(0xffffffffu, s, off);
        float mean = s * (1.f/128.f);
        float d0 = f0.x-mean, d1 = f0.y-mean, d2 = f1.x-mean, d3 = f1.y-mean;
        float d4 = f2.x-mean, d5 = f2.y-mean, d6 = f3.x-mean, d7 = f3.y-mean;
        float sq = d0*d0+d1*d1+d2*d2+d3*d3+d4*d4+d5*d5+d6*d6+d7*d7;
        #pragma unroll
        for (int off = 8; off; off >>= 1) sq += __shfl_xor_sync(0xffffffffu, sq, off);
        float inv = rsqrtf(sq * (1.f/128.f) + 1e-5f);
        int gr = row0 + (ry << 3) + u;
        float4 o0, o1;
        o0.x = d0*inv*g4a.x + b4a.x;  o0.y = d1*inv*g4a.y + b4a.y;
        o0.z = d2*inv*g4a.z + b4a.z;  o0.w = d3*inv*g4a.w + b4a.w;
        o1.x = d4*inv*g4b.x + b4b.x;  o1.y = d5*inv*g4b.y + b4b.y;
        o1.z = d6*inv*g4b.z + b4b.z;  o1.w = d7*inv*g4b.w + b4b.w;
        *(float4*)&out[(size_t)gr * EFq + (tx << 3)]     = o0;
        *(float4*)&out[(size_t)gr * EFq + (tx << 3) + 4] = o1;
    }
}

// =====================================================================
extern "C" void kernel_launch(void* const* d_in, const int* in_sizes, int n_in,
                              void* d_out, int out_size) {
    const float* X         = (const float*)d_in[0];
    const float* mask      = (const float*)d_in[1];
    const float* atom_mask = (const float*)d_in[4];
    const float* W         = (const float*)d_in[5];
    const float* gamma_    = (const float*)d_in[6];
    const float* beta_     = (const float*)d_in[7];
    float* out = (float*)d_out;

    float* out_tail = (out_size >= Mrows * (EFq + 1)) ? (out + (size_t)Mrows * EFq)
                                                      : nullptr;

    topk_kernel<<<Bq*Lq, 256>>>(X, mask, out_tail);
    buildX2_kernel<<<(Bq*Lq + 255)/256, 256>>>(X);
    transposeW_kernel<<<(EFq*EDGE_INq + 255)/256, 256>>>(W);

    cudaFuncSetAttribute(fused_gemm_kernel,
                         cudaFuncAttributeMaxDynamicSharedMemorySize, SMEM_BYTES);
    fused_gemm_kernel<<<Mrows/BM, 256, SMEM_BYTES>>>(atom_mask, gamma_, beta_, out);
}

// round 4
// speedup vs baseline: 2.3370x; 2.3370x over previous
#include <cuda_runtime.h>
#include <cstdint>
#include <math.h>

#define Bq 2
#define Lq 1024
#define Aq 14
#define Kq 30
#define EFq 128
#define EDGE_INq 3152
#define Mrows (Bq*Lq*Kq)      // 61440
#define BM 128
#define NCHUNK 99             // ceil(3152/32); padded K = 3168

typedef uint32_t u32;

// ---- scratch (__device__ globals) ----
__device__ int g_Eidx[Mrows];
__device__ __align__(16) float g_X2[Bq*Lq*Aq*3];
__device__ __align__(16) float g_Wtile[NCHUNK*4096];  // [chunk][k 0..31][n 0..127] tf32

__constant__ float c_freq[8] = {
    1.0f, 0.31622776601683794f, 0.1f, 0.031622776601683794f,
    0.01f, 0.0031622776601683794f, 0.001f, 0.00031622776601683794f
};

__device__ __forceinline__ u32 f2tf32(float v) {
    u32 u; asm("cvt.rna.tf32.f32 %0, %1;" : "=r"(u) : "f"(v)); return u;
}
__device__ __forceinline__ u32 smem_u32(const void* p) {
    u32 a; asm("{ .reg .u64 t; cvta.to.shared.u64 t, %1; cvt.u32.u64 %0, t; }"
               : "=r"(a) : "l"(p));
    return a;
}
__device__ __forceinline__ void mma_tf32(float* d, const u32* a, const u32* b) {
    asm volatile("mma.sync.aligned.m16n8k8.row.col.f32.tf32.tf32.f32 "
        "{%0,%1,%2,%3}, {%4,%5,%6,%7}, {%8,%9}, {%0,%1,%2,%3};"
        : "+f"(d[0]), "+f"(d[1]), "+f"(d[2]), "+f"(d[3])
        : "r"(a[0]), "r"(a[1]), "r"(a[2]), "r"(a[3]), "r"(b[0]), "r"(b[1]));
}
#define CP_ASYNC16(dst, src) asm volatile( \
    "cp.async.ca.shared.global [%0], [%1], 16;" :: "r"(dst), "l"(src) : "memory")
#define CP_COMMIT() asm volatile("cp.async.commit_group;" ::: "memory")
#define CP_WAIT0()  asm volatile("cp.async.wait_group 0;" ::: "memory")

// =====================================================================
// Kernel 1: topk (unchanged — correct since round 1)
// =====================================================================
__global__ void topk_kernel(const float* __restrict__ X,
                            const float* __restrict__ mask,
                            float* __restrict__ out_tail) {
    __shared__ float Da[Lq];
    __shared__ float svals[8];
    __shared__ int   sidx[8];
    __shared__ float sDmax;

    int bi  = blockIdx.x;
    int b   = bi >> 10;
    int i   = bi & (Lq - 1);
    int tid = threadIdx.x;

    const float* Xb = X + (size_t)b * Lq * Aq * 3;
    float cx = Xb[(i*Aq+1)*3+0];
    float cy = Xb[(i*Aq+1)*3+1];
    float cz = Xb[(i*Aq+1)*3+2];
    float mi = mask[b*Lq + i];

    float lmax = 0.f;
    for (int j = tid; j < Lq; j += 256) {
        float dx = cx - Xb[(j*Aq+1)*3+0];
        float dy = cy - Xb[(j*Aq+1)*3+1];
        float dz = cz - Xb[(j*Aq+1)*3+2];
        float m2 = mi * mask[b*Lq + j];
        float D  = m2 * sqrtf(dx*dx + dy*dy + dz*dz + 1e-6f);
        Da[j] = D;
        lmax = fmaxf(lmax, D);
    }
    #pragma unroll
    for (int off = 16; off; off >>= 1)
        lmax = fmaxf(lmax, __shfl_xor_sync(0xffffffffu, lmax, off));
    if ((tid & 31) == 0) svals[tid >> 5] = lmax;
    __syncthreads();
    if (tid == 0) {
        float m = svals[0];
        for (int w = 1; w < 8; w++) m = fmaxf(m, svals[w]);
        sDmax = m;
    }
    __syncthreads();
    float Dmax = sDmax;
    for (int j = tid; j < Lq; j += 256) {
        float m2 = mi * mask[b*Lq + j];
        Da[j] += 2.f * (1.f - m2) * Dmax;
    }
    __syncthreads();

    for (int k = 0; k < Kq; k++) {
        float bv = 3.4e38f; int bj = 0x7fffffff;
        for (int j = tid; j < Lq; j += 256) {
            float v = Da[j];
            if (v < bv) { bv = v; bj = j; }
        }
        #pragma unroll
        for (int off = 16; off; off >>= 1) {
            float ov = __shfl_down_sync(0xffffffffu, bv, off);
            int   oj = __shfl_down_sync(0xffffffffu, bj, off);
            if (ov < bv || (ov == bv && oj < bj)) { bv = ov; bj = oj; }
        }
        if ((tid & 31) == 0) { svals[tid >> 5] = bv; sidx[tid >> 5] = bj; }
        __syncthreads();
        if (tid == 0) {
            for (int w = 1; w < 8; w++) {
                float v = svals[w]; int jj = sidx[w];
                if (v < bv || (v == bv && jj < bj)) { bv = v; bj = jj; }
            }
            int orow = bi * Kq + k;
            g_Eidx[orow] = bj;
            if (out_tail) out_tail[orow] = (float)bj;
            Da[bj] = 3.4e38f;
        }
        __syncthreads();
    }
}

// =====================================================================
// Kernel 2: build X2 with virtual Cb
// =====================================================================
__global__ void buildX2_kernel(const float* __restrict__ X) {
    int t = blockIdx.x * blockDim.x + threadIdx.x;
    if (t >= Bq * Lq) return;
    const float* xr = X + (size_t)t * Aq * 3;
    float* o = g_X2 + (size_t)t * Aq * 3;
    #pragma unroll
    for (int a = 0; a < Aq*3; a++) o[a] = xr[a];
    float Nx = xr[0],  Ny = xr[1],  Nz = xr[2];
    float Cax= xr[3],  Cay= xr[4],  Caz= xr[5];
    float Cx = xr[6],  Cy = xr[7],  Cz = xr[8];
    float bx = Cax - Nx, by = Cay - Ny, bz = Caz - Nz;
    float cx = Cx - Cax, cy = Cy - Cay, cz = Cz - Caz;
    float ax = by*cz - bz*cy;
    float ay = bz*cx - bx*cz;
    float az = bx*cy - by*cx;
    o[12] = -0.58273431f*ax + 0.56802827f*bx - 0.54067466f*cx + Cax;
    o[13] = -0.58273431f*ay + 0.56802827f*by - 0.54067466f*cy + Cay;
    o[14] = -0.58273431f*az + 0.56802827f*bz - 0.54067466f*cz + Caz;
}

// =====================================================================
// Kernel 3: prep W tiles: g_Wtile[chunk][kk][n] = tf32(W[n][32*chunk+kk])
// =====================================================================
__global__ void prepW_kernel(const float* __restrict__ W) {
    int t = blockIdx.x * blockDim.x + threadIdx.x;
    if (t >= NCHUNK * 4096) return;
    int chunk = t >> 12;
    int r  = t & 4095;
    int kk = r >> 7;
    int n  = r & 127;
    int c  = (chunk << 5) + kk;
    float v = (c < EDGE_INq) ? W[(size_t)n * EDGE_INq + c] : 0.f;
    g_Wtile[t] = __uint_as_float(f2tf32(v));
}

// =====================================================================
// Kernel 4: fused featuregen + mma.sync tf32 GEMM + LayerNorm
// BM=128 x BN=128, chunk K=32. 8 warps: wm=wid&3 (32 rows), wn=wid>>2 (64 cols)
// =====================================================================
#define ASTRIDE 36
#define BSTRIDE 132
#define ESTRIDE 132
// byte offsets in dynamic smem
#define OFF_A     0                      // 128*36*4  = 18432
#define OFF_B     18432                  // 32*132*4  = 16896
#define OFF_D     35328                  // 256 f
#define OFF_CO    36352                  // 256 f
#define OFF_DPOS  37376                  // 128 f
#define OFF_IIDX  37888                  // 128 i
#define OFF_JIDX  38400                  // 128 i
#define SM_TOTAL  38912
// epilogue staging overlaps OFF_A (needs 64*132*4 = 33792 <= 35328)

__global__ void __launch_bounds__(256, 2)
fused_hmma_kernel(const float* __restrict__ atom_mask,
                  const float* __restrict__ gamma_,
                  const float* __restrict__ beta_,
                  float* __restrict__ out) {
    extern __shared__ char sm[];
    float* sA   = (float*)(sm + OFF_A);
    float* sB   = (float*)(sm + OFF_B);
    float* sD   = (float*)(sm + OFF_D);
    float* sCo  = (float*)(sm + OFF_CO);
    float* dpos = (float*)(sm + OFF_DPOS);
    int*   iidx = (int*)(sm + OFF_IIDX);
    int*   jidx = (int*)(sm + OFF_JIDX);
    float* sE   = (float*)(sm + OFF_A);   // epilogue reuse

    const u32* sAu = (const u32*)sA;
    const u32* sBu = (const u32*)sB;

    int tid  = threadIdx.x;
    int wid  = tid >> 5, lane = tid & 31;
    int wm   = wid & 3, wn = wid >> 2;
    int lq   = lane >> 2;    // 0..7
    int lr   = lane & 3;     // 0..3
    int row0 = blockIdx.x * BM;

    if (tid < BM) {
        int gr  = row0 + tid;
        int b   = gr / (Lq * Kq);
        int rem = gr - b * (Lq * Kq);
        int i   = rem / Kq;
        int j   = g_Eidx[gr];
        iidx[tid] = b * Lq + i;
        jidx[tid] = b * Lq + j;
        dpos[tid] = (float)(j - i);
    }
    __syncthreads();

    float acc[2][8][4];
    #pragma unroll
    for (int mt = 0; mt < 2; mt++)
        #pragma unroll
        for (int nt = 0; nt < 8; nt++)
            #pragma unroll
            for (int c = 0; c < 4; c++) acc[mt][nt][c] = 0.f;

    u32 sB_base = smem_u32(sB);

    for (int k = 0; k < NCHUNK; k++) {
        __syncthreads();   // guard sA/sB reuse
        // ---- B tile via cp.async (overlaps with gen below) ----
        {
            const float4* bsrc = (const float4*)(g_Wtile + ((size_t)k << 12));
            #pragma unroll
            for (int u = 0; u < 4; u++) {
                int e4 = tid + (u << 8);
                int kk = e4 >> 5, n4 = e4 & 31;
                u32 dst = sB_base + (u32)((kk * BSTRIDE + (n4 << 2)) << 2);
                CP_ASYNC16(dst, bsrc + e4);
            }
            CP_COMMIT();
        }
        // ---- stage D & co for the 2 atom pairs of this chunk ----
        int Pbase = (k == 0) ? 0 : 2*k - 1;
        {
            int l = tid >> 7, row = tid & 127;
            int P = Pbase + l;
            float D = 0.f, co = 0.f;
            if (P <= 195) {
                int p = P / 14, q = P - p * 14;
                const float* xi = g_X2 + iidx[row]*42 + p*3;
                const float* xj = g_X2 + jidx[row]*42 + q*3;
                float dx = xi[0]-xj[0], dy = xi[1]-xj[1], dz = xi[2]-xj[2];
                D  = sqrtf(dx*dx + dy*dy + dz*dz + 1e-6f);
                co = (1.f - atom_mask[iidx[row]*14 + p]) *
                     (1.f - atom_mask[jidx[row]*14 + q]);
            }
            sD[tid] = D; sCo[tid] = co;
        }
        __syncthreads();
        // ---- generate A tile (128 x 32), tf32-rounded ----
        #pragma unroll
        for (int gi = 0; gi < 4; gi++) {
            int g   = tid + (gi << 8);
            int row = g & 127, c4 = g >> 7;   // c4 0..7
            int fc  = (k << 5) + (c4 << 2);
            float v0, v1, v2, v3;
            if (fc < 16) {
                float d = dpos[row];
                float s0, c0, s1, c1, s2, c2, s3, c3;
                int m0 = fc & 7;
                sincosf(d * c_freq[m0+0], &s0, &c0);
                sincosf(d * c_freq[m0+1], &s1, &c1);
                sincosf(d * c_freq[m0+2], &s2, &c2);
                sincosf(d * c_freq[m0+3], &s3, &c3);
                if (fc < 8) { v0=c0; v1=c1; v2=c2; v3=c3; }
                else        { v0=s0; v1=s1; v2=s2; v3=s3; }
            } else {
                int P = (fc - 16) >> 4;
                int l = P - Pbase;
                int e = (l << 7) + row;
                float D = sD[e], co = sCo[e];
                int r0 = (fc - 16) & 15;
                float x0 = (D - (float)(r0+0)*(20.f/15.f)) * 0.8f;
                float x1 = (D - (float)(r0+1)*(20.f/15.f)) * 0.8f;
                float x2 = (D - (float)(r0+2)*(20.f/15.f)) * 0.8f;
                float x3 = (D - (float)(r0+3)*(20.f/15.f)) * 0.8f;
                v0 = co * __expf(-x0*x0);
                v1 = co * __expf(-x1*x1);
                v2 = co * __expf(-x2*x2);
                v3 = co * __expf(-x3*x3);
            }
            uint4 u;
            u.x = f2tf32(v0); u.y = f2tf32(v1); u.z = f2tf32(v2); u.w = f2tf32(v3);
            *(uint4*)&sA[row * ASTRIDE + (c4 << 2)] = u;
        }
        CP_WAIT0();
        __syncthreads();
        // ---- mma phase: 4 k-steps x (2 mtiles x 8 ntiles) ----
        #pragma unroll
        for (int s = 0; s < 4; s++) {
            u32 bfr[8][2];
            #pragma unroll
            for (int nt = 0; nt < 8; nt++) {
                int col = (wn << 6) + (nt << 3) + lq;
                bfr[nt][0] = sBu[((s << 3) + lr    ) * BSTRIDE + col];
                bfr[nt][1] = sBu[((s << 3) + lr + 4) * BSTRIDE + col];
            }
            #pragma unroll
            for (int mt = 0; mt < 2; mt++) {
                int r0 = (wm << 5) + (mt << 4) + lq;
                u32 afr[4];
                afr[0] = sAu[ r0      * ASTRIDE + (s << 3) + lr    ];
                afr[1] = sAu[(r0 + 8) * ASTRIDE + (s << 3) + lr    ];
                afr[2] = sAu[ r0      * ASTRIDE + (s << 3) + lr + 4];
                afr[3] = sAu[(r0 + 8) * ASTRIDE + (s << 3) + lr + 4];
                #pragma unroll
                for (int nt = 0; nt < 8; nt++)
                    mma_tf32(acc[mt][nt], afr, bfr[nt]);
            }
        }
    }

    // ================= epilogue: 2 halves of 64 rows =================
    float4 g4 = *(const float4*)&gamma_[lane << 2];
    float4 b4 = *(const float4*)&beta_ [lane << 2];

    #pragma unroll
    for (int h = 0; h < 2; h++) {
        __syncthreads();
        if ((wm >> 1) == h) {
            #pragma unroll
            for (int mt = 0; mt < 2; mt++) {
                int rl = (wm << 5) + (mt << 4) + lq - (h << 6);
                #pragma unroll
                for (int nt = 0; nt < 8; nt++) {
                    int col = (wn << 6) + (nt << 3) + (lr << 1);
                    *(float2*)&sE[ rl      * ESTRIDE + col] =
                        make_float2(acc[mt][nt][0], acc[mt][nt][1]);
                    *(float2*)&sE[(rl + 8) * ESTRIDE + col] =
                        make_float2(acc[mt][nt][2], acc[mt][nt][3]);
                }
            }
        }
        __syncthreads();
        // LayerNorm: 8 warps x 8 rows
        #pragma unroll
        for (int rr = 0; rr < 8; rr++) {
            int rl = (wid << 3) + rr;
            float4 v = *(const float4*)&sE[rl * ESTRIDE + (lane << 2)];
            float s  = v.x + v.y + v.z + v.w;
            float sq = v.x*v.x + v.y*v.y + v.z*v.z + v.w*v.w;
            #pragma unroll
            for (int off = 16; off; off >>= 1) {
                s  += __shfl_xor_sync(0xffffffffu, s,  off);
                sq += __shfl_xor_sync(0xffffffffu, sq, off);
            }
            float mean = s * (1.f/128.f);
            float var  = sq * (1.f/128.f) - mean * mean;
            float inv  = rsqrtf(var + 1e-5f);
            int gr = row0 + (h << 6) + rl;
            float4 o;
            o.x = (v.x - mean)*inv*g4.x + b4.x;
            o.y = (v.y - mean)*inv*g4.y + b4.y;
            o.z = (v.z - mean)*inv*g4.z + b4.z;
            o.w = (v.w - mean)*inv*g4.w + b4.w;
            *(float4*)&out[(size_t)gr * EFq + (lane << 2)] = o;
        }
    }
}

// =====================================================================
extern "C" void kernel_launch(void* const* d_in, const int* in_sizes, int n_in,
                              void* d_out, int out_size) {
    const float* X         = (const float*)d_in[0];
    const float* mask      = (const float*)d_in[1];
    const float* atom_mask = (const float*)d_in[4];
    const float* W         = (const float*)d_in[5];
    const float* gamma_    = (const float*)d_in[6];
    const float* beta_     = (const float*)d_in[7];
    float* out = (float*)d_out;

    float* out_tail = (out_size >= Mrows * (EFq + 1)) ? (out + (size_t)Mrows * EFq)
                                                      : nullptr;

    topk_kernel<<<Bq*Lq, 256>>>(X, mask, out_tail);
    buildX2_kernel<<<(Bq*Lq + 255)/256, 256>>>(X);
    prepW_kernel<<<(NCHUNK*4096 + 255)/256, 256>>>(W);

    cudaFuncSetAttribute(fused_hmma_kernel,
                         cudaFuncAttributeMaxDynamicSharedMemorySize, SM_TOTAL);
    fused_hmma_kernel<<<Mrows/BM, 256, SM_TOTAL>>>(atom_mask, gamma_, beta_, out);
}